// round 9
// baseline (speedup 1.0000x reference)
#include <cuda_runtime.h>

#define PATCHES  196
#define FEATS    784
#define CLASSES  10
#define BATCH    1024

// Scratch: z-features, [B, 196] float4 (patch-major, wire-minor) = feats[B,784]
__device__ __align__(16) float4 g_feats[BATCH * PATCHES];

// RX rotation on an amplitude pair: a_i' = c a_i - i s a_j ; a_j' = c a_j - i s a_i
__device__ __forceinline__ void rx_pair(float* re, float* im, int i, int j,
                                        float c, float s) {
    float r0 = re[i], i0 = im[i], r1 = re[j], i1 = im[j];
    re[i] = fmaf(c, r0,  s * i1);
    im[i] = fmaf(c, i0, -s * r1);
    re[j] = fmaf(c, r1,  s * i0);
    im[j] = fmaf(c, i1, -s * r0);
}

// ---------------- Phase 1: dense circuit kernel ----------------
// grid 784 x 256 threads: global thread g = one (batch, patch) pair.
__global__ __launch_bounds__(256)
void quanv_circuit_kernel(const float* __restrict__ x,   // [1024,1,28,28]
                          const float* __restrict__ qp)  // [3,4]
{
    // Layer-0 combo (RZ0 folded into closed-form sign/i structure) and
    // layer-1 RZ phase factors. index = s*4 + i
    __shared__ float s_c0r[8], s_c0i[8];
    __shared__ float s_p1r[8], s_p1i[8];

    const int tid = threadIdx.x;
    const int g   = blockIdx.x * 256 + tid;
    const int b   = g / PATCHES;
    const int p   = g - b * PATCHES;
    const int r   = p / 14, c = p - (p / 14) * 14;

    // Kick off global x loads first; overlap with phase setup.
    const float* xb = x + (size_t)b * 784;
    float2 top = *(const float2*)(xb + (2 * r) * 28 + 2 * c);
    float2 bot = *(const float2*)(xb + (2 * r + 1) * 28 + 2 * c);

    if (tid < 8) {
        int s = tid >> 2, i = tid & 3;
        {
            float qh = qp[2 * s], ql = qp[2 * s + 1];
            float th = 0.5f * (((i & 2) ? qh : -qh) + ((i & 1) ? ql : -ql));
            float pr, pi;
            __sincosf(th, &pi, &pr);
            // amp0: (pr, pi); amp1/amp3: (pi, -pr); amp2: (-pr, -pi)
            float cr, ci;
            if (i == 0)      { cr =  pr; ci =  pi; }
            else if (i == 2) { cr = -pr; ci = -pi; }
            else             { cr =  pi; ci = -pr; }
            s_c0r[tid] = cr; s_c0i[tid] = ci;
        }
        {
            float qh = qp[4 + 2 * s], ql = qp[4 + 2 * s + 1];
            float th = 0.5f * (((i & 2) ? qh : -qh) + ((i & 1) ? ql : -ql));
            __sincosf(th, &s_p1i[tid], &s_p1r[tid]);
        }
    }
    __syncthreads();

    float ang[4] = {top.x, top.y, bot.x, bot.y};
    float cs[4], sn[4];
#pragma unroll
    for (int w = 0; w < 4; w++)
        __sincosf(ang[w] * 0.5f, &sn[w], &cs[w]);

    float z[4];
    // Two independent 2-qubit substates: s=0 -> wires(0,1), s=1 -> wires(2,3)
#pragma unroll
    for (int s = 0; s < 2; s++) {
        const float ch = cs[2 * s],     sh = sn[2 * s];
        const float cl = cs[2 * s + 1], sl = sn[2 * s + 1];

        // layer 0 (RX closed form on |00>) + CNOT + RZ0, folded
        const float chcl = ch * cl, chsl = ch * sl;
        const float shsl = sh * sl, shcl = sh * cl;
        float re[4], im[4];
        re[0] = chcl * s_c0r[s * 4 + 0];  im[0] = chcl * s_c0i[s * 4 + 0];
        re[1] = chsl * s_c0r[s * 4 + 1];  im[1] = chsl * s_c0i[s * 4 + 1];
        re[2] = shsl * s_c0r[s * 4 + 2];  im[2] = shsl * s_c0i[s * 4 + 2];
        re[3] = shcl * s_c0r[s * 4 + 3];  im[3] = shcl * s_c0i[s * 4 + 3];

        // layer 1: RX both wires, CNOT, RZ
        rx_pair(re, im, 0, 2, ch, sh);
        rx_pair(re, im, 1, 3, ch, sh);
        rx_pair(re, im, 0, 1, cl, sl);
        rx_pair(re, im, 2, 3, cl, sl);
        { float t;
          t = re[2]; re[2] = re[3]; re[3] = t;
          t = im[2]; im[2] = im[3]; im[3] = t; }
#pragma unroll
        for (int i = 0; i < 4; i++) {
            float pr = s_p1r[s * 4 + i], pi = s_p1i[s * 4 + i];
            float r0 = re[i], i0 = im[i];
            re[i] = fmaf(pr, r0, -pi * i0);
            im[i] = fmaf(pr, i0,  pi * r0);
        }

        // layer 2: RX both wires; final CNOT folded into z_lo remap;
        // final RZ is a dead phase under |.|^2
        rx_pair(re, im, 0, 2, ch, sh);
        rx_pair(re, im, 1, 3, ch, sh);
        rx_pair(re, im, 0, 1, cl, sl);
        rx_pair(re, im, 2, 3, cl, sl);

        float p0 = fmaf(re[0], re[0], im[0] * im[0]);
        float p1 = fmaf(re[1], re[1], im[1] * im[1]);
        float p2 = fmaf(re[2], re[2], im[2] * im[2]);
        float p3 = fmaf(re[3], re[3], im[3] * im[3]);
        // CNOT would swap p2<->p3: z_hi invariant, z_lo uses swapped pair.
        z[2 * s]     = (p0 + p1) - (p2 + p3);
        z[2 * s + 1] = (p0 + p3) - (p1 + p2);
    }

    g_feats[g] = make_float4(z[0], z[1], z[2], z[3]);
}

// ---------------- Phase 2: logits + log_softmax ----------------
// One warp per batch row. grid 128 x 256 (8 warps/block -> 1024 warps).
__global__ __launch_bounds__(256)
void quanv_logits_kernel(const float* __restrict__ W,    // [10,784]
                         const float* __restrict__ bias, // [10]
                         float* __restrict__ out)        // [1024,10]
{
    const int wp   = threadIdx.x >> 5;
    const int lane = threadIdx.x & 31;
    const int row  = blockIdx.x * 8 + wp;

    const float4* F = g_feats + row * PATCHES;   // 196 float4
    float acc[CLASSES];
#pragma unroll
    for (int c = 0; c < CLASSES; c++) acc[c] = 0.f;

#pragma unroll
    for (int k = 0; k < 6; k++) {
        float4 f = F[lane + 32 * k];
#pragma unroll
        for (int c = 0; c < CLASSES; c++) {
            float4 w = ((const float4*)(W + c * FEATS))[lane + 32 * k];
            acc[c] = fmaf(f.x, w.x, acc[c]);
            acc[c] = fmaf(f.y, w.y, acc[c]);
            acc[c] = fmaf(f.z, w.z, acc[c]);
            acc[c] = fmaf(f.w, w.w, acc[c]);
        }
    }
    if (lane < 4) {  // remainder chunk: float4 indices 192..195
        float4 f = F[192 + lane];
#pragma unroll
        for (int c = 0; c < CLASSES; c++) {
            float4 w = ((const float4*)(W + c * FEATS))[192 + lane];
            acc[c] = fmaf(f.x, w.x, acc[c]);
            acc[c] = fmaf(f.y, w.y, acc[c]);
            acc[c] = fmaf(f.z, w.z, acc[c]);
            acc[c] = fmaf(f.w, w.w, acc[c]);
        }
    }

    // Butterfly reduce each class accumulator across the warp.
#pragma unroll
    for (int c = 0; c < CLASSES; c++) {
#pragma unroll
        for (int off = 16; off > 0; off >>= 1)
            acc[c] += __shfl_xor_sync(0xffffffffu, acc[c], off);
    }

    if (lane == 0) {
        float lg[CLASSES];
        float m = -3.4e38f;
#pragma unroll
        for (int c = 0; c < CLASSES; c++) {
            lg[c] = acc[c] + bias[c];
            m = fmaxf(m, lg[c]);
        }
        float sum = 0.f;
#pragma unroll
        for (int c = 0; c < CLASSES; c++) sum += __expf(lg[c] - m);
        float lse = m + __logf(sum);
        float* o = out + (size_t)row * CLASSES;
#pragma unroll
        for (int c = 0; c < CLASSES; c++) o[c] = lg[c] - lse;
    }
}

extern "C" void kernel_launch(void* const* d_in, const int* in_sizes, int n_in,
                              void* d_out, int out_size) {
    const float* x  = (const float*)d_in[0];   // [1024,1,28,28]
    const float* qp = (const float*)d_in[1];   // [3,4]
    const float* W  = (const float*)d_in[2];   // [10,784]
    const float* b  = (const float*)d_in[3];   // [10]
    float* out = (float*)d_out;                // [1024,10]
    quanv_circuit_kernel<<<784, 256>>>(x, qp);
    quanv_logits_kernel<<<128, 256>>>(W, b, out);
}

// round 10
// speedup vs baseline: 1.0201x; 1.0201x over previous
#include <cuda_runtime.h>

#define PATCHES  196
#define FEATS    784
#define CLASSES  10
#define BATCH    1024

// Scratch: z-features, [B, 196] float4 (patch-major, wire-minor) = feats[B,784]
__device__ __align__(16) float4 g_feats[BATCH * PATCHES];

// RX rotation on an amplitude pair: a_i' = c a_i - i s a_j ; a_j' = c a_j - i s a_i
__device__ __forceinline__ void rx_pair(float* re, float* im, int i, int j,
                                        float c, float s) {
    float r0 = re[i], i0 = im[i], r1 = re[j], i1 = im[j];
    re[i] = fmaf(c, r0,  s * i1);
    im[i] = fmaf(c, i0, -s * r1);
    re[j] = fmaf(c, r1,  s * i0);
    im[j] = fmaf(c, i1, -s * r0);
}

// ---------------- Phase 1: dense circuit kernel ----------------
// grid 784 x 256 threads: global thread g = one (batch, patch) pair.
__global__ __launch_bounds__(256)
void quanv_circuit_kernel(const float* __restrict__ x,   // [1024,1,28,28]
                          const float* __restrict__ qp)  // [3,4]
{
    // Layer-0 combo (RZ0 folded into closed-form sign/i structure) and
    // layer-1 RZ phase factors. index = s*4 + i
    __shared__ float s_c0r[8], s_c0i[8];
    __shared__ float s_p1r[8], s_p1i[8];

    const int tid = threadIdx.x;
    const int g   = blockIdx.x * 256 + tid;
    const int b   = g / PATCHES;
    const int p   = g - b * PATCHES;
    const int r   = p / 14, c = p - (p / 14) * 14;

    // Kick off global x loads first; overlap with phase setup.
    const float* xb = x + (size_t)b * 784;
    float2 top = *(const float2*)(xb + (2 * r) * 28 + 2 * c);
    float2 bot = *(const float2*)(xb + (2 * r + 1) * 28 + 2 * c);

    if (tid < 8) {
        int s = tid >> 2, i = tid & 3;
        {
            float qh = qp[2 * s], ql = qp[2 * s + 1];
            float th = 0.5f * (((i & 2) ? qh : -qh) + ((i & 1) ? ql : -ql));
            float pr, pi;
            __sincosf(th, &pi, &pr);
            // amp0: (pr, pi); amp1/amp3: (pi, -pr); amp2: (-pr, -pi)
            float cr, ci;
            if (i == 0)      { cr =  pr; ci =  pi; }
            else if (i == 2) { cr = -pr; ci = -pi; }
            else             { cr =  pi; ci = -pr; }
            s_c0r[tid] = cr; s_c0i[tid] = ci;
        }
        {
            float qh = qp[4 + 2 * s], ql = qp[4 + 2 * s + 1];
            float th = 0.5f * (((i & 2) ? qh : -qh) + ((i & 1) ? ql : -ql));
            __sincosf(th, &s_p1i[tid], &s_p1r[tid]);
        }
    }
    __syncthreads();

    float ang[4] = {top.x, top.y, bot.x, bot.y};
    float cs[4], sn[4];
#pragma unroll
    for (int w = 0; w < 4; w++)
        __sincosf(ang[w] * 0.5f, &sn[w], &cs[w]);

    float z[4];
    // Two independent 2-qubit substates: s=0 -> wires(0,1), s=1 -> wires(2,3)
#pragma unroll
    for (int s = 0; s < 2; s++) {
        const float ch = cs[2 * s],     sh = sn[2 * s];
        const float cl = cs[2 * s + 1], sl = sn[2 * s + 1];

        // layer 0 (RX closed form on |00>) + CNOT + RZ0, folded
        const float chcl = ch * cl, chsl = ch * sl;
        const float shsl = sh * sl, shcl = sh * cl;
        float re[4], im[4];
        re[0] = chcl * s_c0r[s * 4 + 0];  im[0] = chcl * s_c0i[s * 4 + 0];
        re[1] = chsl * s_c0r[s * 4 + 1];  im[1] = chsl * s_c0i[s * 4 + 1];
        re[2] = shsl * s_c0r[s * 4 + 2];  im[2] = shsl * s_c0i[s * 4 + 2];
        re[3] = shcl * s_c0r[s * 4 + 3];  im[3] = shcl * s_c0i[s * 4 + 3];

        // layer 1: RX both wires, CNOT, RZ
        rx_pair(re, im, 0, 2, ch, sh);
        rx_pair(re, im, 1, 3, ch, sh);
        rx_pair(re, im, 0, 1, cl, sl);
        rx_pair(re, im, 2, 3, cl, sl);
        { float t;
          t = re[2]; re[2] = re[3]; re[3] = t;
          t = im[2]; im[2] = im[3]; im[3] = t; }
#pragma unroll
        for (int i = 0; i < 4; i++) {
            float pr = s_p1r[s * 4 + i], pi = s_p1i[s * 4 + i];
            float r0 = re[i], i0 = im[i];
            re[i] = fmaf(pr, r0, -pi * i0);
            im[i] = fmaf(pr, i0,  pi * r0);
        }

        // layer 2: RX both wires; final CNOT folded into z_lo remap;
        // final RZ is a dead phase under |.|^2
        rx_pair(re, im, 0, 2, ch, sh);
        rx_pair(re, im, 1, 3, ch, sh);
        rx_pair(re, im, 0, 1, cl, sl);
        rx_pair(re, im, 2, 3, cl, sl);

        float p0 = fmaf(re[0], re[0], im[0] * im[0]);
        float p1 = fmaf(re[1], re[1], im[1] * im[1]);
        float p2 = fmaf(re[2], re[2], im[2] * im[2]);
        float p3 = fmaf(re[3], re[3], im[3] * im[3]);
        // CNOT would swap p2<->p3: z_hi invariant, z_lo uses swapped pair.
        z[2 * s]     = (p0 + p1) - (p2 + p3);
        z[2 * s + 1] = (p0 + p3) - (p1 + p2);
    }

    g_feats[g] = make_float4(z[0], z[1], z[2], z[3]);
}

// ---------------- Phase 2: logits + log_softmax ----------------
// ONE BLOCK PER BATCH ROW (grid=1024, 224 threads). Thread t<196 owns feats
// chunk float4[t] and accumulates partials for all 10 classes; two-level
// block reduction; warp 0 does log_softmax.
__global__ __launch_bounds__(224)
void quanv_logits_kernel(const float* __restrict__ W,    // [10,784]
                         const float* __restrict__ bias, // [10]
                         float* __restrict__ out)        // [1024,10]
{
    __shared__ float s_part[7][CLASSES];

    const int row  = blockIdx.x;
    const int tid  = threadIdx.x;
    const int wp   = tid >> 5, lane = tid & 31;

    float acc[CLASSES];
#pragma unroll
    for (int c = 0; c < CLASSES; c++) acc[c] = 0.f;

    if (tid < PATCHES) {
        float4 f = g_feats[row * PATCHES + tid];
#pragma unroll
        for (int c = 0; c < CLASSES; c++) {
            float4 w = ((const float4*)(W + c * FEATS))[tid];
            float t0 = fmaf(f.x, w.x, f.y * w.y);
            float t1 = fmaf(f.z, w.z, f.w * w.w);
            acc[c] = t0 + t1;
        }
    }

    // Warp-level butterfly per class; lane 0 stores partials.
#pragma unroll
    for (int c = 0; c < CLASSES; c++) {
#pragma unroll
        for (int off = 16; off > 0; off >>= 1)
            acc[c] += __shfl_xor_sync(0xffffffffu, acc[c], off);
    }
    if (lane == 0) {
#pragma unroll
        for (int c = 0; c < CLASSES; c++) s_part[wp][c] = acc[c];
    }
    __syncthreads();

    // Warp 0: combine 7 warp partials, then log_softmax over 10 logits.
    if (wp == 0) {
        float v;
        if (lane < CLASSES) {
            v = bias[lane];
#pragma unroll
            for (int w = 0; w < 7; w++) v += s_part[w][lane];
        } else {
            v = -3.4e38f;
        }
        float m = v;
#pragma unroll
        for (int off = 16; off > 0; off >>= 1)
            m = fmaxf(m, __shfl_xor_sync(0xffffffffu, m, off));
        float e = (lane < CLASSES) ? __expf(v - m) : 0.f;
        float sum = e;
#pragma unroll
        for (int off = 16; off > 0; off >>= 1)
            sum += __shfl_xor_sync(0xffffffffu, sum, off);
        float lse = m + __logf(sum);
        if (lane < CLASSES)
            out[(size_t)row * CLASSES + lane] = v - lse;
    }
}

extern "C" void kernel_launch(void* const* d_in, const int* in_sizes, int n_in,
                              void* d_out, int out_size) {
    const float* x  = (const float*)d_in[0];   // [1024,1,28,28]
    const float* qp = (const float*)d_in[1];   // [3,4]
    const float* W  = (const float*)d_in[2];   // [10,784]
    const float* b  = (const float*)d_in[3];   // [10]
    float* out = (float*)d_out;                // [1024,10]
    quanv_circuit_kernel<<<784, 256>>>(x, qp);
    quanv_logits_kernel<<<1024, 224>>>(W, b, out);
}

// round 11
// speedup vs baseline: 1.0304x; 1.0101x over previous
#include <cuda_runtime.h>

#define PATCHES  196
#define FEATS    784
#define CLASSES  10
#define BATCH    1024

// Scratch: z-features, [B, 196] float4 (patch-major, wire-minor) = feats[B,784]
__device__ __align__(16) float4 g_feats[BATCH * PATCHES];

// RX rotation on an amplitude pair: a_i' = c a_i - i s a_j ; a_j' = c a_j - i s a_i
__device__ __forceinline__ void rx_pair(float* re, float* im, int i, int j,
                                        float c, float s) {
    float r0 = re[i], i0 = im[i], r1 = re[j], i1 = im[j];
    re[i] = fmaf(c, r0,  s * i1);
    im[i] = fmaf(c, i0, -s * r1);
    re[j] = fmaf(c, r1,  s * i0);
    im[j] = fmaf(c, i1, -s * r0);
}

// ---------------- Phase 1: dense circuit kernel ----------------
// grid 784 x 256 threads: global thread g = one (batch, patch) pair.
__global__ __launch_bounds__(256)
void quanv_circuit_kernel(const float* __restrict__ x,   // [1024,1,28,28]
                          const float* __restrict__ qp)  // [3,4]
{
    // Layer-0 combo (RZ0 folded into closed-form sign/i structure) and
    // layer-1 RZ phase factors. index = s*4 + i
    __shared__ float s_c0r[8], s_c0i[8];
    __shared__ float s_p1r[8], s_p1i[8];

    const int tid = threadIdx.x;
    const int g   = blockIdx.x * 256 + tid;
    const int b   = g / PATCHES;
    const int p   = g - b * PATCHES;
    const int r   = p / 14, c = p - (p / 14) * 14;

    // Kick off global x loads first; overlap with phase setup.
    const float* xb = x + (size_t)b * 784;
    float2 top = *(const float2*)(xb + (2 * r) * 28 + 2 * c);
    float2 bot = *(const float2*)(xb + (2 * r + 1) * 28 + 2 * c);

    if (tid < 8) {
        int s = tid >> 2, i = tid & 3;
        {
            float qh = qp[2 * s], ql = qp[2 * s + 1];
            float th = 0.5f * (((i & 2) ? qh : -qh) + ((i & 1) ? ql : -ql));
            float pr, pi;
            __sincosf(th, &pi, &pr);
            // amp0: (pr, pi); amp1/amp3: (pi, -pr); amp2: (-pr, -pi)
            float cr, ci;
            if (i == 0)      { cr =  pr; ci =  pi; }
            else if (i == 2) { cr = -pr; ci = -pi; }
            else             { cr =  pi; ci = -pr; }
            s_c0r[tid] = cr; s_c0i[tid] = ci;
        }
        {
            float qh = qp[4 + 2 * s], ql = qp[4 + 2 * s + 1];
            float th = 0.5f * (((i & 2) ? qh : -qh) + ((i & 1) ? ql : -ql));
            __sincosf(th, &s_p1i[tid], &s_p1r[tid]);
        }
    }
    __syncthreads();

    float ang[4] = {top.x, top.y, bot.x, bot.y};
    float cs[4], sn[4];
#pragma unroll
    for (int w = 0; w < 4; w++)
        __sincosf(ang[w] * 0.5f, &sn[w], &cs[w]);

    float z[4];
    // Two independent 2-qubit substates: s=0 -> wires(0,1), s=1 -> wires(2,3)
#pragma unroll
    for (int s = 0; s < 2; s++) {
        const float ch = cs[2 * s],     sh = sn[2 * s];
        const float cl = cs[2 * s + 1], sl = sn[2 * s + 1];

        // layer 0 (RX closed form on |00>) + CNOT + RZ0, folded
        const float chcl = ch * cl, chsl = ch * sl;
        const float shsl = sh * sl, shcl = sh * cl;
        float re[4], im[4];
        re[0] = chcl * s_c0r[s * 4 + 0];  im[0] = chcl * s_c0i[s * 4 + 0];
        re[1] = chsl * s_c0r[s * 4 + 1];  im[1] = chsl * s_c0i[s * 4 + 1];
        re[2] = shsl * s_c0r[s * 4 + 2];  im[2] = shsl * s_c0i[s * 4 + 2];
        re[3] = shcl * s_c0r[s * 4 + 3];  im[3] = shcl * s_c0i[s * 4 + 3];

        // layer 1: RX both wires, CNOT, RZ
        rx_pair(re, im, 0, 2, ch, sh);
        rx_pair(re, im, 1, 3, ch, sh);
        rx_pair(re, im, 0, 1, cl, sl);
        rx_pair(re, im, 2, 3, cl, sl);
        { float t;
          t = re[2]; re[2] = re[3]; re[3] = t;
          t = im[2]; im[2] = im[3]; im[3] = t; }
#pragma unroll
        for (int i = 0; i < 4; i++) {
            float pr = s_p1r[s * 4 + i], pi = s_p1i[s * 4 + i];
            float r0 = re[i], i0 = im[i];
            re[i] = fmaf(pr, r0, -pi * i0);
            im[i] = fmaf(pr, i0,  pi * r0);
        }

        // layer 2: RX both wires; final CNOT folded into z_lo remap;
        // final RZ is a dead phase under |.|^2
        rx_pair(re, im, 0, 2, ch, sh);
        rx_pair(re, im, 1, 3, ch, sh);
        rx_pair(re, im, 0, 1, cl, sl);
        rx_pair(re, im, 2, 3, cl, sl);

        float p0 = fmaf(re[0], re[0], im[0] * im[0]);
        float p1 = fmaf(re[1], re[1], im[1] * im[1]);
        float p2 = fmaf(re[2], re[2], im[2] * im[2]);
        float p3 = fmaf(re[3], re[3], im[3] * im[3]);
        // CNOT would swap p2<->p3: z_hi invariant, z_lo uses swapped pair.
        z[2 * s]     = (p0 + p1) - (p2 + p3);
        z[2 * s + 1] = (p0 + p3) - (p1 + p2);
    }

    g_feats[g] = make_float4(z[0], z[1], z[2], z[3]);
}

// ---------------- Phase 2: logits + log_softmax ----------------
// ONE BLOCK PER BATCH ROW (grid=1024, 224 threads). Thread t<196 owns feats
// chunk float4[t] and accumulates partials for all 10 classes; two-level
// block reduction; warp 0 does log_softmax.
__global__ __launch_bounds__(224)
void quanv_logits_kernel(const float* __restrict__ W,    // [10,784]
                         const float* __restrict__ bias, // [10]
                         float* __restrict__ out)        // [1024,10]
{
    __shared__ float s_part[7][CLASSES];

    const int row  = blockIdx.x;
    const int tid  = threadIdx.x;
    const int wp   = tid >> 5, lane = tid & 31;

    float acc[CLASSES];
#pragma unroll
    for (int c = 0; c < CLASSES; c++) acc[c] = 0.f;

    if (tid < PATCHES) {
        float4 f = g_feats[row * PATCHES + tid];
#pragma unroll
        for (int c = 0; c < CLASSES; c++) {
            float4 w = ((const float4*)(W + c * FEATS))[tid];
            float t0 = fmaf(f.x, w.x, f.y * w.y);
            float t1 = fmaf(f.z, w.z, f.w * w.w);
            acc[c] = t0 + t1;
        }
    }

    // Warp-level butterfly per class; lane 0 stores partials.
#pragma unroll
    for (int c = 0; c < CLASSES; c++) {
#pragma unroll
        for (int off = 16; off > 0; off >>= 1)
            acc[c] += __shfl_xor_sync(0xffffffffu, acc[c], off);
    }
    if (lane == 0) {
#pragma unroll
        for (int c = 0; c < CLASSES; c++) s_part[wp][c] = acc[c];
    }
    __syncthreads();

    // Warp 0: combine 7 warp partials, then log_softmax over 10 logits.
    if (wp == 0) {
        float v;
        if (lane < CLASSES) {
            v = bias[lane];
#pragma unroll
            for (int w = 0; w < 7; w++) v += s_part[w][lane];
        } else {
            v = -3.4e38f;
        }
        float m = v;
#pragma unroll
        for (int off = 16; off > 0; off >>= 1)
            m = fmaxf(m, __shfl_xor_sync(0xffffffffu, m, off));
        float e = (lane < CLASSES) ? __expf(v - m) : 0.f;
        float sum = e;
#pragma unroll
        for (int off = 16; off > 0; off >>= 1)
            sum += __shfl_xor_sync(0xffffffffu, sum, off);
        float lse = m + __logf(sum);
        if (lane < CLASSES)
            out[(size_t)row * CLASSES + lane] = v - lse;
    }
}

extern "C" void kernel_launch(void* const* d_in, const int* in_sizes, int n_in,
                              void* d_out, int out_size) {
    const float* x  = (const float*)d_in[0];   // [1024,1,28,28]
    const float* qp = (const float*)d_in[1];   // [3,4]
    const float* W  = (const float*)d_in[2];   // [10,784]
    const float* b  = (const float*)d_in[3];   // [10]
    float* out = (float*)d_out;                // [1024,10]
    quanv_circuit_kernel<<<784, 256>>>(x, qp);
    quanv_logits_kernel<<<1024, 224>>>(W, b, out);
}

// round 12
// speedup vs baseline: 1.0436x; 1.0128x over previous
#include <cuda_runtime.h>

#define PATCHES  196
#define FEATS    784
#define CLASSES  10
#define BATCH    1024

// Scratch: z-features, [B, 196] float4 (patch-major, wire-minor) = feats[B,784]
__device__ __align__(16) float4 g_feats[BATCH * PATCHES];

// RX rotation on an amplitude pair: a_i' = c a_i - i s a_j ; a_j' = c a_j - i s a_i
__device__ __forceinline__ void rx_pair(float* re, float* im, int i, int j,
                                        float c, float s) {
    float r0 = re[i], i0 = im[i], r1 = re[j], i1 = im[j];
    re[i] = fmaf(c, r0,  s * i1);
    im[i] = fmaf(c, i0, -s * r1);
    re[j] = fmaf(c, r1,  s * i0);
    im[j] = fmaf(c, i1, -s * r0);
}

// ---------------- Phase 1: dense circuit kernel ----------------
// grid 784 x 256 threads: global thread g = one (batch, patch) pair.
__global__ __launch_bounds__(256)
void quanv_circuit_kernel(const float* __restrict__ x,   // [1024,1,28,28]
                          const float* __restrict__ qp)  // [3,4]
{
    // Layer-0 combo (RZ0 folded into closed-form sign/i structure) and
    // layer-1 RZ phase factors. index = s*4 + i
    __shared__ float s_c0r[8], s_c0i[8];
    __shared__ float s_p1r[8], s_p1i[8];

    const int tid = threadIdx.x;
    const int g   = blockIdx.x * 256 + tid;
    const int b   = g / PATCHES;
    const int p   = g - b * PATCHES;
    const int r   = p / 14, c = p - (p / 14) * 14;

    // Kick off global x loads first; overlap with phase setup.
    const float* xb = x + (size_t)b * 784;
    float2 top = *(const float2*)(xb + (2 * r) * 28 + 2 * c);
    float2 bot = *(const float2*)(xb + (2 * r + 1) * 28 + 2 * c);

    if (tid < 8) {
        int s = tid >> 2, i = tid & 3;
        {
            float qh = qp[2 * s], ql = qp[2 * s + 1];
            float th = 0.5f * (((i & 2) ? qh : -qh) + ((i & 1) ? ql : -ql));
            float pr, pi;
            __sincosf(th, &pi, &pr);
            // amp0: (pr, pi); amp1/amp3: (pi, -pr); amp2: (-pr, -pi)
            float cr, ci;
            if (i == 0)      { cr =  pr; ci =  pi; }
            else if (i == 2) { cr = -pr; ci = -pi; }
            else             { cr =  pi; ci = -pr; }
            s_c0r[tid] = cr; s_c0i[tid] = ci;
        }
        {
            float qh = qp[4 + 2 * s], ql = qp[4 + 2 * s + 1];
            float th = 0.5f * (((i & 2) ? qh : -qh) + ((i & 1) ? ql : -ql));
            __sincosf(th, &s_p1i[tid], &s_p1r[tid]);
        }
    }
    __syncthreads();

    float ang[4] = {top.x, top.y, bot.x, bot.y};
    float cs[4], sn[4];
#pragma unroll
    for (int w = 0; w < 4; w++)
        __sincosf(ang[w] * 0.5f, &sn[w], &cs[w]);

    float z[4];
    // Two independent 2-qubit substates: s=0 -> wires(0,1), s=1 -> wires(2,3)
#pragma unroll
    for (int s = 0; s < 2; s++) {
        const float ch = cs[2 * s],     sh = sn[2 * s];
        const float cl = cs[2 * s + 1], sl = sn[2 * s + 1];

        // layer 0 (RX closed form on |00>) + CNOT + RZ0, folded
        const float chcl = ch * cl, chsl = ch * sl;
        const float shsl = sh * sl, shcl = sh * cl;
        float re[4], im[4];
        re[0] = chcl * s_c0r[s * 4 + 0];  im[0] = chcl * s_c0i[s * 4 + 0];
        re[1] = chsl * s_c0r[s * 4 + 1];  im[1] = chsl * s_c0i[s * 4 + 1];
        re[2] = shsl * s_c0r[s * 4 + 2];  im[2] = shsl * s_c0i[s * 4 + 2];
        re[3] = shcl * s_c0r[s * 4 + 3];  im[3] = shcl * s_c0i[s * 4 + 3];

        // layer 1: RX both wires, CNOT, RZ
        rx_pair(re, im, 0, 2, ch, sh);
        rx_pair(re, im, 1, 3, ch, sh);
        rx_pair(re, im, 0, 1, cl, sl);
        rx_pair(re, im, 2, 3, cl, sl);
        { float t;
          t = re[2]; re[2] = re[3]; re[3] = t;
          t = im[2]; im[2] = im[3]; im[3] = t; }
#pragma unroll
        for (int i = 0; i < 4; i++) {
            float pr = s_p1r[s * 4 + i], pi = s_p1i[s * 4 + i];
            float r0 = re[i], i0 = im[i];
            re[i] = fmaf(pr, r0, -pi * i0);
            im[i] = fmaf(pr, i0,  pi * r0);
        }

        // layer 2: RX both wires; final CNOT folded into z_lo remap;
        // final RZ is a dead phase under |.|^2
        rx_pair(re, im, 0, 2, ch, sh);
        rx_pair(re, im, 1, 3, ch, sh);
        rx_pair(re, im, 0, 1, cl, sl);
        rx_pair(re, im, 2, 3, cl, sl);

        float p0 = fmaf(re[0], re[0], im[0] * im[0]);
        float p1 = fmaf(re[1], re[1], im[1] * im[1]);
        float p2 = fmaf(re[2], re[2], im[2] * im[2]);
        float p3 = fmaf(re[3], re[3], im[3] * im[3]);
        // CNOT would swap p2<->p3: z_hi invariant, z_lo uses swapped pair.
        z[2 * s]     = (p0 + p1) - (p2 + p3);
        z[2 * s + 1] = (p0 + p3) - (p1 + p2);
    }

    g_feats[g] = make_float4(z[0], z[1], z[2], z[3]);
}

// ---------------- Phase 2: logits + log_softmax ----------------
// ONE BLOCK PER BATCH ROW (grid=1024, 224 threads). Thread t<196 owns feats
// chunk float4[t] and accumulates partials for all 10 classes; two-level
// block reduction; warp 0 does log_softmax.
__global__ __launch_bounds__(224)
void quanv_logits_kernel(const float* __restrict__ W,    // [10,784]
                         const float* __restrict__ bias, // [10]
                         float* __restrict__ out)        // [1024,10]
{
    __shared__ float s_part[7][CLASSES];

    const int row  = blockIdx.x;
    const int tid  = threadIdx.x;
    const int wp   = tid >> 5, lane = tid & 31;

    float acc[CLASSES];
#pragma unroll
    for (int c = 0; c < CLASSES; c++) acc[c] = 0.f;

    if (tid < PATCHES) {
        float4 f = g_feats[row * PATCHES + tid];
#pragma unroll
        for (int c = 0; c < CLASSES; c++) {
            float4 w = ((const float4*)(W + c * FEATS))[tid];
            float t0 = fmaf(f.x, w.x, f.y * w.y);
            float t1 = fmaf(f.z, w.z, f.w * w.w);
            acc[c] = t0 + t1;
        }
    }

    // Warp-level butterfly per class; lane 0 stores partials.
#pragma unroll
    for (int c = 0; c < CLASSES; c++) {
#pragma unroll
        for (int off = 16; off > 0; off >>= 1)
            acc[c] += __shfl_xor_sync(0xffffffffu, acc[c], off);
    }
    if (lane == 0) {
#pragma unroll
        for (int c = 0; c < CLASSES; c++) s_part[wp][c] = acc[c];
    }
    __syncthreads();

    // Warp 0: combine 7 warp partials, then log_softmax over 10 logits.
    if (wp == 0) {
        float v;
        if (lane < CLASSES) {
            v = bias[lane];
#pragma unroll
            for (int w = 0; w < 7; w++) v += s_part[w][lane];
        } else {
            v = -3.4e38f;
        }
        float m = v;
#pragma unroll
        for (int off = 16; off > 0; off >>= 1)
            m = fmaxf(m, __shfl_xor_sync(0xffffffffu, m, off));
        float e = (lane < CLASSES) ? __expf(v - m) : 0.f;
        float sum = e;
#pragma unroll
        for (int off = 16; off > 0; off >>= 1)
            sum += __shfl_xor_sync(0xffffffffu, sum, off);
        float lse = m + __logf(sum);
        if (lane < CLASSES)
            out[(size_t)row * CLASSES + lane] = v - lse;
    }
}

extern "C" void kernel_launch(void* const* d_in, const int* in_sizes, int n_in,
                              void* d_out, int out_size) {
    const float* x  = (const float*)d_in[0];   // [1024,1,28,28]
    const float* qp = (const float*)d_in[1];   // [3,4]
    const float* W  = (const float*)d_in[2];   // [10,784]
    const float* b  = (const float*)d_in[3];   // [10]
    float* out = (float*)d_out;                // [1024,10]
    quanv_circuit_kernel<<<784, 256>>>(x, qp);
    quanv_logits_kernel<<<1024, 224>>>(W, b, out);
}